// round 15
// baseline (speedup 1.0000x reference)
#include <cuda_runtime.h>

// Segment mean pooling: x [524288,128] f32, pointer [1025] i32 -> out [1024,128] f32.
//
//   Step 1: cudaMemsetAsync(out, 0) — graph-capturable memset node.
//   Step 2: grid 1024 x 512-row chunks, 256 threads = 8 warps x 32 float4-
//     columns, stride-8 rows, unroll 4, __ldcs streaming loads (proven R14
//     engine). NEW: no smem, no __syncthreads — each warp flushes its own
//     inv-scaled partial per segment intersection with one red.global.v4.f32
//     per lane (no return trip, ~0.85cyc/lane). Warps stream their rows with
//     zero intra-CTA coupling. Sum of all inv-scaled partials == segment mean.

#define D_FEAT 128
#define D4 (D_FEAT / 4)     // 32 float4 per row
#define CHUNK 512           // rows per CTA

__device__ __forceinline__ void red_add_v4(float* addr, float a, float b, float c, float d) {
    asm volatile("red.global.add.v4.f32 [%0], {%1, %2, %3, %4};"
                 :: "l"(addr), "f"(a), "f"(b), "f"(c), "f"(d) : "memory");
}

__global__ __launch_bounds__(256) void seg_accum_kernel(
    const float4* __restrict__ x4,
    const int* __restrict__ ptr,
    float* __restrict__ out,
    int n_rows, int n_segs)
{
    const int base = blockIdx.x * CHUNK;
    if (base >= n_rows) return;
    const int cend = min(base + CHUNK, n_rows);
    const int c4 = threadIdx.x & 31;   // float4 column 0..31
    const int r  = threadIdx.x >> 5;   // row-lane warp 0..7

    // First segment overlapping the chunk (CTA-uniform -> broadcast L1 hits).
    int lo = 0, hi = n_segs - 1;
    while (lo < hi) {
        int mid = (lo + hi + 1) >> 1;
        if (__ldg(ptr + mid) <= base) lo = mid; else hi = mid - 1;
    }
    int seg = lo;

    for (;;) {
        const int seg_beg = __ldg(ptr + seg);
        const int seg_end = __ldg(ptr + seg + 1);
        const int s = max(seg_beg, base);
        const int e = min(seg_end, cend);

        float4 acc = make_float4(0.f, 0.f, 0.f, 0.f);
        #pragma unroll 4
        for (int row = s + r; row < e; row += 8) {
            const float4 v = __ldcs(x4 + (size_t)row * D4 + c4);  // streaming
            acc.x += v.x; acc.y += v.y; acc.z += v.z; acc.w += v.w;
        }

        // Per-warp flush: this warp touched rows iff s + r < e.
        if (s + r < e) {
            const float inv = 1.0f / (float)(seg_end - seg_beg);
            float* o = out + (size_t)seg * D_FEAT + c4 * 4;
            red_add_v4(o, acc.x * inv, acc.y * inv, acc.z * inv, acc.w * inv);
        }
        if (seg_end >= cend) break;
        seg++;
    }
}

extern "C" void kernel_launch(void* const* d_in, const int* in_sizes, int n_in,
                              void* d_out, int out_size)
{
    const float4* x4  = (const float4*)d_in[0];
    const int*    ptr = (const int*)d_in[1];
    float*        out = (float*)d_out;

    const int n_rows = in_sizes[0] / D_FEAT;   // 524288
    const int n_segs = in_sizes[1] - 1;        // 1024

    cudaMemsetAsync(out, 0, (size_t)out_size * sizeof(float), 0);

    const int n_chunks = (n_rows + CHUNK - 1) / CHUNK;   // 1024
    seg_accum_kernel<<<n_chunks, 256>>>(x4, ptr, out, n_rows, n_segs);
}